// round 1
// baseline (speedup 1.0000x reference)
#include <cuda_runtime.h>
#include <cuda_bf16.h>
#include <cstdint>

// ---------------------------------------------------------------------------
// ViT block: x -> LN1 -> MHSA(+rel-pos bias) -> +x -> LN2 -> MLP(GELU) -> +.
// Shapes: B=16, C=384, H=W=32 (N=1024), NH=8, HD=48, MID=384, HID=1536.
// All fp32, [B, C, N] channel-major layout throughout (matches input/output).
// ---------------------------------------------------------------------------

#define BB   16
#define CC   384
#define NN   1024
#define NHH  8
#define HDD  48
#define MIDD 384
#define HIDD 1536

// Scratch (device globals: allocation-free, graph-safe)
__device__ float g_ln [BB * CC   * NN];   // LN1 output, reused for LN2 output
__device__ float g_q  [BB * MIDD * NN];
__device__ float g_kv [BB * 2 * MIDD * NN];
__device__ float g_ao [BB * MIDD * NN];   // attention output (pre-proj)
__device__ float g_y1 [BB * CC   * NN];   // x + attn-proj (residual 1)
__device__ float g_mid[BB * HIDD * NN];   // MLP hidden

// ---------------------------------------------------------------------------
// LayerNorm over channel axis, per token. Layout [B, C, N], thread = token.
// Consecutive threads -> consecutive n -> fully coalesced for every c.
// ---------------------------------------------------------------------------
__global__ __launch_bounds__(256)
void ln_kernel(const float* __restrict__ x, const float* __restrict__ g,
               const float* __restrict__ beta, float* __restrict__ out)
{
    const int b = blockIdx.y;
    const int n = blockIdx.x * 256 + threadIdx.x;
    const float* xp = x + (size_t)b * CC * NN + n;

    float sum = 0.f, sq = 0.f;
    #pragma unroll 4
    for (int c = 0; c < CC; c++) {
        float v = xp[(size_t)c * NN];
        sum += v; sq += v * v;
    }
    const float mean = sum * (1.f / CC);
    float var = sq * (1.f / CC) - mean * mean;
    var = var < 0.f ? 0.f : var;
    const float rstd = rsqrtf(var + 1e-5f);

    float* op = out + (size_t)b * CC * NN + n;
    #pragma unroll 4
    for (int c = 0; c < CC; c++) {
        float v = xp[(size_t)c * NN];
        op[(size_t)c * NN] = (v - mean) * rstd * g[c] + beta[c];
    }
}

// ---------------------------------------------------------------------------
// Tiled GEMM: out[b][o][n] = sum_c W[o][c] * A[b][c][n] + bias[o]  (+epilogue)
// W row-major [O, K]; A [B, K, N]; out [B, O, N].
// 64x64 tile, BK=16, 256 threads, 4x4 per-thread microtile.
// EPI: 0 = bias only, 1 = + residual, 2 = exact GELU.
// ---------------------------------------------------------------------------
template<int EPI>
__global__ __launch_bounds__(256)
void gemm_kernel(const float* __restrict__ W, const float* __restrict__ A,
                 const float* __restrict__ bias, const float* __restrict__ res,
                 float* __restrict__ out, int O, int K)
{
    const int b  = blockIdx.z;
    const int n0 = blockIdx.x * 64;
    const int m0 = blockIdx.y * 64;

    __shared__ __align__(16) float Ws[16][68];
    __shared__ __align__(16) float As[16][68];

    const int tid = threadIdx.x;
    const int tx  = tid & 15;
    const int ty  = tid >> 4;

    float acc[4][4] = {};

    const float* Ab = A + (size_t)b * K * NN;

    for (int k0 = 0; k0 < K; k0 += 16) {
        // W tile: [64 rows of O] x [16 of K], store transposed Ws[k][m]
        {
            const int kk = tid & 15;
            #pragma unroll
            for (int i = 0; i < 4; i++) {
                const int mm = (tid >> 4) + i * 16;
                Ws[kk][mm] = W[(size_t)(m0 + mm) * K + (k0 + kk)];
            }
        }
        // A tile: [16 of K] x [64 of N]
        {
            const int nn = tid & 63;
            #pragma unroll
            for (int i = 0; i < 4; i++) {
                const int kk = (tid >> 6) + i * 4;
                As[kk][nn] = Ab[(size_t)(k0 + kk) * NN + (n0 + nn)];
            }
        }
        __syncthreads();

        #pragma unroll
        for (int kk = 0; kk < 16; kk++) {
            const float4 a4 = *(const float4*)&Ws[kk][ty * 4];
            const float4 b4 = *(const float4*)&As[kk][tx * 4];
            acc[0][0] += a4.x * b4.x; acc[0][1] += a4.x * b4.y;
            acc[0][2] += a4.x * b4.z; acc[0][3] += a4.x * b4.w;
            acc[1][0] += a4.y * b4.x; acc[1][1] += a4.y * b4.y;
            acc[1][2] += a4.y * b4.z; acc[1][3] += a4.y * b4.w;
            acc[2][0] += a4.z * b4.x; acc[2][1] += a4.z * b4.y;
            acc[2][2] += a4.z * b4.z; acc[2][3] += a4.z * b4.w;
            acc[3][0] += a4.w * b4.x; acc[3][1] += a4.w * b4.y;
            acc[3][2] += a4.w * b4.z; acc[3][3] += a4.w * b4.w;
        }
        __syncthreads();
    }

    #pragma unroll
    for (int i = 0; i < 4; i++) {
        const int m = m0 + ty * 4 + i;
        const float bv = bias[m];
        #pragma unroll
        for (int j = 0; j < 4; j++) {
            const int n = n0 + tx * 4 + j;
            const size_t idx = ((size_t)b * O + m) * NN + n;
            float v = acc[i][j] + bv;
            if (EPI == 1) v += res[idx];
            if (EPI == 2) v = 0.5f * v * (1.f + erff(v * 0.7071067811865476f));
            out[idx] = v;
        }
    }
}

// ---------------------------------------------------------------------------
// Fused attention with online softmax + relative position bias.
// Grid: (N/128, NH, B). Block: 128 threads, thread = 1 query row.
// q, kv layout: [B, rows, N], rows = h*48 + d (kv: +384 offset for V).
// Bias: idx(n,m) = (hn-hm+31)*63 + (wn-wm+31); window staged in SMEM
// once per block (2205 gathers) instead of per-(n,m) (131072 gathers).
// ---------------------------------------------------------------------------
__global__ __launch_bounds__(128)
void attn_kernel(const float* __restrict__ q, const float* __restrict__ kv,
                 const float* __restrict__ rpb, float* __restrict__ o)
{
    const int tid = threadIdx.x;
    const int n   = blockIdx.x * 128 + tid;
    const int h   = blockIdx.y;
    const int b   = blockIdx.z;

    __shared__ __align__(16) float ks[64][56];
    __shared__ __align__(16) float vs[64][56];
    __shared__ float bias_s[35][64];

    // hn spans [r0, r0+3] for this block (32 tokens per image row)
    const int r0 = blockIdx.x * 4;
    for (int e = tid; e < 35 * 63; e += 128) {
        const int a   = e / 63;       // a = hn - hm - (r0 - 31), in [0,35)
        const int dwi = e % 63;
        bias_s[a][dwi] = rpb[((size_t)((a + r0) * 63 + dwi)) * NHH + h];
    }

    // q row -> registers (scale folded in)
    const float scale = 0.14433756729740643f;  // 48^-0.5
    float qr[48];
    const float* qp = q + ((size_t)(b * MIDD + h * HDD)) * NN + n;
    #pragma unroll
    for (int d = 0; d < 48; d++) qr[d] = qp[(size_t)d * NN] * scale;

    float oacc[48];
    #pragma unroll
    for (int d = 0; d < 48; d++) oacc[d] = 0.f;
    float mrun = -1e30f, lrun = 0.f;

    const int hn_local = tid >> 5;   // hn - r0
    const int wn       = n & 31;

    const float* kp = kv + ((size_t)(b * 2 * MIDD + h * HDD)) * NN;
    const float* vp = kp + (size_t)MIDD * NN;

    for (int m0 = 0; m0 < NN; m0 += 64) {
        __syncthreads();
        // Load K/V tile: lanes vary j (coalesced), 2 d-rows per pass
        #pragma unroll
        for (int dd = 0; dd < 48; dd += 2) {
            const int d = dd + (tid >> 6);
            const int j = tid & 63;
            ks[j][d] = kp[(size_t)d * NN + m0 + j];
            vs[j][d] = vp[(size_t)d * NN + m0 + j];
        }
        __syncthreads();

        for (int j = 0; j < 64; j++) {
            const int m  = m0 + j;
            const int hm = m >> 5;
            const int wm = m & 31;
            float s = bias_s[hn_local + 31 - hm][wn - wm + 31];

            const float4* kk4 = (const float4*)&ks[j][0];
            #pragma unroll
            for (int d4 = 0; d4 < 12; d4++) {
                const float4 kq = kk4[d4];
                s += qr[d4*4+0] * kq.x + qr[d4*4+1] * kq.y
                   + qr[d4*4+2] * kq.z + qr[d4*4+3] * kq.w;
            }

            float p;
            if (s > mrun) {
                const float corr = __expf(mrun - s);
                lrun *= corr;
                #pragma unroll
                for (int d = 0; d < 48; d++) oacc[d] *= corr;
                mrun = s;
                p = 1.f;
            } else {
                p = __expf(s - mrun);
            }
            lrun += p;

            const float4* vv4 = (const float4*)&vs[j][0];
            #pragma unroll
            for (int d4 = 0; d4 < 12; d4++) {
                const float4 vq = vv4[d4];
                oacc[d4*4+0] += p * vq.x; oacc[d4*4+1] += p * vq.y;
                oacc[d4*4+2] += p * vq.z; oacc[d4*4+3] += p * vq.w;
            }
        }
    }

    const float inv = 1.f / lrun;
    float* op = o + ((size_t)(b * MIDD + h * HDD)) * NN + n;
    #pragma unroll
    for (int d = 0; d < 48; d++) op[(size_t)d * NN] = oacc[d] * inv;
}

// ---------------------------------------------------------------------------
// Launch sequence (graph-capturable: kernel launches only)
// ---------------------------------------------------------------------------
extern "C" void kernel_launch(void* const* d_in, const int* in_sizes, int n_in,
                              void* d_out, int out_size)
{
    const float* x     = (const float*)d_in[0];
    const float* rpb   = (const float*)d_in[1];
    // d_in[2] = rel_index (int32) : unused, recomputed algebraically
    const float* ln1_g = (const float*)d_in[3];
    const float* ln1_b = (const float*)d_in[4];
    const float* ln2_g = (const float*)d_in[5];
    const float* ln2_b = (const float*)d_in[6];
    const float* wq    = (const float*)d_in[7];
    const float* bq    = (const float*)d_in[8];
    const float* wkv   = (const float*)d_in[9];
    const float* bkv   = (const float*)d_in[10];
    const float* wproj = (const float*)d_in[11];
    const float* bproj = (const float*)d_in[12];
    const float* w1    = (const float*)d_in[13];
    const float* b1    = (const float*)d_in[14];
    const float* w2    = (const float*)d_in[15];
    const float* b2    = (const float*)d_in[16];
    float* out = (float*)d_out;

    float *p_ln, *p_q, *p_kv, *p_ao, *p_y1, *p_mid;
    cudaGetSymbolAddress((void**)&p_ln,  g_ln);
    cudaGetSymbolAddress((void**)&p_q,   g_q);
    cudaGetSymbolAddress((void**)&p_kv,  g_kv);
    cudaGetSymbolAddress((void**)&p_ao,  g_ao);
    cudaGetSymbolAddress((void**)&p_y1,  g_y1);
    cudaGetSymbolAddress((void**)&p_mid, g_mid);

    const dim3 lnGrid(NN / 256, BB);

    // LN1
    ln_kernel<<<lnGrid, 256>>>(x, ln1_g, ln1_b, p_ln);
    // Q = wq @ ln1 + bq
    gemm_kernel<0><<<dim3(NN/64, MIDD/64,   BB), 256>>>(wq,  p_ln, bq,  nullptr, p_q,  MIDD,   CC);
    // KV = wkv @ ln1 + bkv
    gemm_kernel<0><<<dim3(NN/64, 2*MIDD/64, BB), 256>>>(wkv, p_ln, bkv, nullptr, p_kv, 2*MIDD, CC);
    // Attention (softmax(qk^T*scale + bias) @ v)
    attn_kernel<<<dim3(NN/128, NHH, BB), 128>>>(p_q, p_kv, rpb, p_ao);
    // y1 = x + wproj @ attn_out + bproj
    gemm_kernel<1><<<dim3(NN/64, CC/64, BB), 256>>>(wproj, p_ao, bproj, x, p_y1, CC, MIDD);
    // LN2
    ln_kernel<<<lnGrid, 256>>>(p_y1, ln2_g, ln2_b, p_ln);
    // hidden = gelu(w1 @ ln2 + b1)
    gemm_kernel<2><<<dim3(NN/64, HIDD/64, BB), 256>>>(w1, p_ln, b1, nullptr, p_mid, HIDD, CC);
    // out = y1 + w2 @ hidden + b2
    gemm_kernel<1><<<dim3(NN/64, CC/64, BB), 256>>>(w2, p_mid, b2, p_y1, out, CC, HIDD);
}

// round 4
// speedup vs baseline: 1.5691x; 1.5691x over previous
#include <cuda_runtime.h>
#include <cuda_bf16.h>
#include <cstdint>

// ---------------------------------------------------------------------------
// ViT block. B=16, C=384, N=1024 (32x32), NH=8, HD=48, MID=384, HID=1536.
// Layout [B, C, N] everywhere, fp32 in gmem.
// Projection GEMMs: mma.sync m16n8k16 bf16 (legacy HMMA — the only tensor path
// reachable under the harness's compute_100 target; tcgen05 needs sm_100a).
// Accuracy: 3-product hi/lo bf16 split => ~fp32-grade results.
// ---------------------------------------------------------------------------

#define BB   16
#define CC   384
#define NN   1024
#define NHH  8
#define HDD  48
#define MIDD 384
#define HIDD 1536

// Scratch (device globals: allocation-free, graph-safe)
__device__ float g_ln [BB * CC   * NN];
__device__ float g_q  [BB * MIDD * NN];
__device__ float g_kv [BB * 2 * MIDD * NN];
__device__ float g_ao [BB * MIDD * NN];
__device__ float g_y1 [BB * CC   * NN];
__device__ float g_mid[BB * HIDD * NN];

__device__ __forceinline__ uint32_t smem_to_u32(const void* p) {
    uint32_t a;
    asm("{ .reg .u64 t; cvta.to.shared.u64 t, %1; cvt.u32.u64 %0, t; }" : "=r"(a) : "l"(p));
    return a;
}
__device__ __forceinline__ void ldmx4(uint32_t* r, uint32_t addr) {
    asm volatile("ldmatrix.sync.aligned.m8n8.x4.shared.b16 {%0,%1,%2,%3}, [%4];"
                 : "=r"(r[0]), "=r"(r[1]), "=r"(r[2]), "=r"(r[3]) : "r"(addr));
}
__device__ __forceinline__ void mma16816(float* c, const uint32_t* a,
                                         uint32_t b0, uint32_t b1) {
    asm volatile("mma.sync.aligned.m16n8k16.row.col.f32.bf16.bf16.f32 "
                 "{%0,%1,%2,%3}, {%4,%5,%6,%7}, {%8,%9}, {%0,%1,%2,%3};"
                 : "+f"(c[0]), "+f"(c[1]), "+f"(c[2]), "+f"(c[3])
                 : "r"(a[0]), "r"(a[1]), "r"(a[2]), "r"(a[3]), "r"(b0), "r"(b1));
}

// ---------------------------------------------------------------------------
// LayerNorm over channel axis, per token, layout [B, C, N]. Coalesced in n.
// ---------------------------------------------------------------------------
__global__ __launch_bounds__(256)
void ln_kernel(const float* __restrict__ x, const float* __restrict__ g,
               const float* __restrict__ beta, float* __restrict__ out)
{
    const int b = blockIdx.y;
    const int n = blockIdx.x * 256 + threadIdx.x;
    const float* xp = x + (size_t)b * CC * NN + n;

    float sum = 0.f, sq = 0.f;
    #pragma unroll 4
    for (int c = 0; c < CC; c++) {
        float v = xp[(size_t)c * NN];
        sum += v; sq += v * v;
    }
    const float mean = sum * (1.f / CC);
    float var = sq * (1.f / CC) - mean * mean;
    var = var < 0.f ? 0.f : var;
    const float rstd = rsqrtf(var + 1e-5f);

    float* op = out + (size_t)b * CC * NN + n;
    #pragma unroll 4
    for (int c = 0; c < CC; c++) {
        float v = xp[(size_t)c * NN];
        op[(size_t)c * NN] = (v - mean) * rstd * g[c] + beta[c];
    }
}

// ---------------------------------------------------------------------------
// HMMA GEMM: out[b][o][n] = sum_c W[o][c]*Act[b][c][n] (+bias, +epilogue)
// mma view: D[m=token][n=o], A[m][k]=Act^T (row-major), B[n][k]=W (col-major k x n).
// CTA 128x128, K-chunk 64. 8 warps = 2(m) x 4(n); warp tile 64x32.
// SMEM rows padded to 72 halves (144B stride): conflict-free ldmatrix.
// Epilogue transposes via smem so gmem writes are coalesced.
// EPI: 0 = bias; 1 = bias+residual; 2 = bias+exact GELU.
// ---------------------------------------------------------------------------
#define TILE_HALF  (128 * 72)            // halves per operand tile
#define SM_AHI 0
#define SM_ALO (TILE_HALF * 2)           // byte offsets
#define SM_BHI (TILE_HALF * 4)
#define SM_BLO (TILE_HALF * 6)
#define SM_GEMM_TOTAL (TILE_HALF * 8)    // 73728 B (also covers 128x132 fp32 epi)

union Pack16 { __nv_bfloat162 h2[4]; uint4 u; };

__device__ __forceinline__ void split8(const float* v, Pack16& hu, Pack16& lu) {
    #pragma unroll
    for (int j = 0; j < 4; j++) {
        __nv_bfloat16 h0 = __float2bfloat16(v[2*j]);
        __nv_bfloat16 h1 = __float2bfloat16(v[2*j+1]);
        __nv_bfloat16 l0 = __float2bfloat16(v[2*j]   - __bfloat162float(h0));
        __nv_bfloat16 l1 = __float2bfloat16(v[2*j+1] - __bfloat162float(h1));
        hu.h2[j] = __nv_bfloat162(h0, h1);
        lu.h2[j] = __nv_bfloat162(l0, l1);
    }
}

template<int EPI>
__global__ __launch_bounds__(256, 2)
void mma_gemm(const float* __restrict__ W, const float* __restrict__ Act,
              const float* __restrict__ bias, const float* __restrict__ res,
              float* __restrict__ out, int O, int K)
{
    extern __shared__ __align__(16) char smem[];
    const uint32_t sbase = smem_to_u32(smem);

    const int b   = blockIdx.z;
    const int n0  = blockIdx.x * 128;   // token base
    const int o0  = blockIdx.y * 128;   // out-channel base
    const int tid = threadIdx.x;
    const int wid = tid >> 5;
    const int lane = tid & 31;
    const int wm = wid & 1;             // warp m (token) index: 0..1
    const int wn = wid >> 1;            // warp n (o) index: 0..3

    float acc[4][4][4];
    #pragma unroll
    for (int i = 0; i < 4; i++)
        #pragma unroll
        for (int j = 0; j < 4; j++)
            #pragma unroll
            for (int e = 0; e < 4; e++) acc[i][j][e] = 0.f;

    const float* Ab = Act + (size_t)b * K * NN;

    // ldmatrix per-thread base addresses (row part varies with lane)
    const int a_row  = wm * 64 + (lane & 7) + (lane & 8);          // + mf*16
    const int a_kg   = (lane >> 4);                                 // + ks*2
    const int b_row  = wn * 32 + (lane & 7) + ((lane >> 4) & 1) * 8; // + ng*16
    const int b_kg   = (lane >> 3) & 1;                             // + ks*2

    const int nchunks = K >> 6;
    for (int chunk = 0; chunk < nchunks; chunk++) {
        const int k0 = chunk << 6;

        // ---- A tile: 128 tokens x 64 c (lanes sweep tokens: coalesced) ----
        #pragma unroll
        for (int r = 0; r < 4; r++) {
            const int u = tid + 256 * r;
            const int t = u & 127;
            const int g = u >> 7;
            const float* ap = Ab + (size_t)(k0 + g * 8) * NN + n0 + t;
            float v[8];
            #pragma unroll
            for (int i = 0; i < 8; i++) v[i] = ap[(size_t)i * NN];
            Pack16 hu, lu; split8(v, hu, lu);
            const uint32_t off = (uint32_t)(t * 72 + g * 8) * 2;
            *(uint4*)(smem + SM_AHI + off) = hu.u;
            *(uint4*)(smem + SM_ALO + off) = lu.u;
        }
        // ---- B tile: 128 o x 64 c (contiguous along c: coalesced) ----
        #pragma unroll
        for (int r = 0; r < 4; r++) {
            const int u = tid + 256 * r;
            const int g = u & 7;
            const int row = u >> 3;
            const float4* wp = (const float4*)(W + (size_t)(o0 + row) * K + k0 + g * 8);
            const float4 w0 = wp[0], w1 = wp[1];
            float v[8] = {w0.x, w0.y, w0.z, w0.w, w1.x, w1.y, w1.z, w1.w};
            Pack16 hu, lu; split8(v, hu, lu);
            const uint32_t off = (uint32_t)(row * 72 + g * 8) * 2;
            *(uint4*)(smem + SM_BHI + off) = hu.u;
            *(uint4*)(smem + SM_BLO + off) = lu.u;
        }
        __syncthreads();

        #pragma unroll
        for (int ks = 0; ks < 4; ks++) {
            // B fragments: 2 x ldmatrix.x4 per product -> 4 n-frags (b0,b1 pairs)
            uint32_t bh[8], bl[8];
            #pragma unroll
            for (int ng = 0; ng < 2; ng++) {
                const uint32_t boff =
                    (uint32_t)((b_row + ng * 16) * 72 + (ks * 2 + b_kg) * 8) * 2;
                ldmx4(&bh[ng * 4], sbase + SM_BHI + boff);
                ldmx4(&bl[ng * 4], sbase + SM_BLO + boff);
            }
            #pragma unroll
            for (int mf = 0; mf < 4; mf++) {
                const uint32_t aoff =
                    (uint32_t)((a_row + mf * 16) * 72 + (ks * 2 + a_kg) * 8) * 2;
                uint32_t ah[4], al[4];
                ldmx4(ah, sbase + SM_AHI + aoff);
                ldmx4(al, sbase + SM_ALO + aoff);
                #pragma unroll
                for (int nf = 0; nf < 4; nf++) {
                    const int bi = (nf >> 1) * 4 + (nf & 1) * 2;
                    mma16816(acc[mf][nf], ah, bh[bi], bh[bi + 1]);
                    mma16816(acc[mf][nf], ah, bl[bi], bl[bi + 1]);
                    mma16816(acc[mf][nf], al, bh[bi], bh[bi + 1]);
                }
            }
        }
        __syncthreads();
    }

    // ---- Epilogue: transpose via smem, coalesced gmem writes ----
    float* Cs = (float*)smem;  // [128 o][132 m]
    #pragma unroll
    for (int mf = 0; mf < 4; mf++) {
        const int m = wm * 64 + mf * 16 + (lane >> 2);
        #pragma unroll
        for (int nf = 0; nf < 4; nf++) {
            const int ol = wn * 32 + nf * 8 + (lane & 3) * 2;
            Cs[ ol      * 132 + m    ] = acc[mf][nf][0];
            Cs[(ol + 1) * 132 + m    ] = acc[mf][nf][1];
            Cs[ ol      * 132 + m + 8] = acc[mf][nf][2];
            Cs[(ol + 1) * 132 + m + 8] = acc[mf][nf][3];
        }
    }
    __syncthreads();

    #pragma unroll 4
    for (int i = 0; i < 64; i++) {
        const int idx = tid + 256 * i;
        const int ol = idx >> 7;
        const int m  = idx & 127;
        const int o  = o0 + ol;
        float v = Cs[ol * 132 + m] + bias[o];
        const size_t gidx = ((size_t)b * O + o) * NN + n0 + m;
        if (EPI == 1) v += res[gidx];
        if (EPI == 2) v = 0.5f * v * (1.f + erff(v * 0.7071067811865476f));
        out[gidx] = v;   // lanes sweep m: coalesced
    }
}

// ---------------------------------------------------------------------------
// Fused attention (round-1 version: online softmax, SMEM-staged rel-pos bias)
// ---------------------------------------------------------------------------
__global__ __launch_bounds__(128)
void attn_kernel(const float* __restrict__ q, const float* __restrict__ kv,
                 const float* __restrict__ rpb, float* __restrict__ o)
{
    const int tid = threadIdx.x;
    const int n   = blockIdx.x * 128 + tid;
    const int h   = blockIdx.y;
    const int b   = blockIdx.z;

    __shared__ __align__(16) float ks[64][56];
    __shared__ __align__(16) float vs[64][56];
    __shared__ float bias_s[35][64];

    const int r0 = blockIdx.x * 4;
    for (int e = tid; e < 35 * 63; e += 128) {
        const int a   = e / 63;
        const int dwi = e % 63;
        bias_s[a][dwi] = rpb[((size_t)((a + r0) * 63 + dwi)) * NHH + h];
    }

    const float scale = 0.14433756729740643f;
    float qr[48];
    const float* qp = q + ((size_t)(b * MIDD + h * HDD)) * NN + n;
    #pragma unroll
    for (int d = 0; d < 48; d++) qr[d] = qp[(size_t)d * NN] * scale;

    float oacc[48];
    #pragma unroll
    for (int d = 0; d < 48; d++) oacc[d] = 0.f;
    float mrun = -1e30f, lrun = 0.f;

    const int hn_local = tid >> 5;
    const int wn       = n & 31;

    const float* kp = kv + ((size_t)(b * 2 * MIDD + h * HDD)) * NN;
    const float* vp = kp + (size_t)MIDD * NN;

    for (int m0 = 0; m0 < NN; m0 += 64) {
        __syncthreads();
        #pragma unroll
        for (int dd = 0; dd < 48; dd += 2) {
            const int d = dd + (tid >> 6);
            const int j = tid & 63;
            ks[j][d] = kp[(size_t)d * NN + m0 + j];
            vs[j][d] = vp[(size_t)d * NN + m0 + j];
        }
        __syncthreads();

        for (int j = 0; j < 64; j++) {
            const int m  = m0 + j;
            const int hm = m >> 5;
            const int wm = m & 31;
            float s = bias_s[hn_local + 31 - hm][wn - wm + 31];

            const float4* kk4 = (const float4*)&ks[j][0];
            #pragma unroll
            for (int d4 = 0; d4 < 12; d4++) {
                const float4 kq = kk4[d4];
                s += qr[d4*4+0] * kq.x + qr[d4*4+1] * kq.y
                   + qr[d4*4+2] * kq.z + qr[d4*4+3] * kq.w;
            }

            float p;
            if (s > mrun) {
                const float corr = __expf(mrun - s);
                lrun *= corr;
                #pragma unroll
                for (int d = 0; d < 48; d++) oacc[d] *= corr;
                mrun = s;
                p = 1.f;
            } else {
                p = __expf(s - mrun);
            }
            lrun += p;

            const float4* vv4 = (const float4*)&vs[j][0];
            #pragma unroll
            for (int d4 = 0; d4 < 12; d4++) {
                const float4 vq = vv4[d4];
                oacc[d4*4+0] += p * vq.x; oacc[d4*4+1] += p * vq.y;
                oacc[d4*4+2] += p * vq.z; oacc[d4*4+3] += p * vq.w;
            }
        }
    }

    const float inv = 1.f / lrun;
    float* op = o + ((size_t)(b * MIDD + h * HDD)) * NN + n;
    #pragma unroll
    for (int d = 0; d < 48; d++) op[(size_t)d * NN] = oacc[d] * inv;
}

// ---------------------------------------------------------------------------
// Launch sequence (kernel launches only: graph-capturable)
// ---------------------------------------------------------------------------
extern "C" void kernel_launch(void* const* d_in, const int* in_sizes, int n_in,
                              void* d_out, int out_size)
{
    const float* x     = (const float*)d_in[0];
    const float* rpb   = (const float*)d_in[1];
    const float* ln1_g = (const float*)d_in[3];
    const float* ln1_b = (const float*)d_in[4];
    const float* ln2_g = (const float*)d_in[5];
    const float* ln2_b = (const float*)d_in[6];
    const float* wq    = (const float*)d_in[7];
    const float* bq    = (const float*)d_in[8];
    const float* wkv   = (const float*)d_in[9];
    const float* bkv   = (const float*)d_in[10];
    const float* wproj = (const float*)d_in[11];
    const float* bproj = (const float*)d_in[12];
    const float* w1    = (const float*)d_in[13];
    const float* b1    = (const float*)d_in[14];
    const float* w2    = (const float*)d_in[15];
    const float* b2    = (const float*)d_in[16];
    float* out = (float*)d_out;

    float *p_ln, *p_q, *p_kv, *p_ao, *p_y1, *p_mid;
    cudaGetSymbolAddress((void**)&p_ln,  g_ln);
    cudaGetSymbolAddress((void**)&p_q,   g_q);
    cudaGetSymbolAddress((void**)&p_kv,  g_kv);
    cudaGetSymbolAddress((void**)&p_ao,  g_ao);
    cudaGetSymbolAddress((void**)&p_y1,  g_y1);
    cudaGetSymbolAddress((void**)&p_mid, g_mid);

    cudaFuncSetAttribute(mma_gemm<0>, cudaFuncAttributeMaxDynamicSharedMemorySize, SM_GEMM_TOTAL);
    cudaFuncSetAttribute(mma_gemm<1>, cudaFuncAttributeMaxDynamicSharedMemorySize, SM_GEMM_TOTAL);
    cudaFuncSetAttribute(mma_gemm<2>, cudaFuncAttributeMaxDynamicSharedMemorySize, SM_GEMM_TOTAL);

    const dim3 lnGrid(NN / 256, BB);

    // LN1
    ln_kernel<<<lnGrid, 256>>>(x, ln1_g, ln1_b, p_ln);
    // Q = wq @ ln1 + bq
    mma_gemm<0><<<dim3(NN/128, MIDD/128,   BB), 256, SM_GEMM_TOTAL>>>(wq,  p_ln, bq,  nullptr, p_q,  MIDD,   CC);
    // KV = wkv @ ln1 + bkv
    mma_gemm<0><<<dim3(NN/128, 2*MIDD/128, BB), 256, SM_GEMM_TOTAL>>>(wkv, p_ln, bkv, nullptr, p_kv, 2*MIDD, CC);
    // Attention
    attn_kernel<<<dim3(NN/128, NHH, BB), 128>>>(p_q, p_kv, rpb, p_ao);
    // y1 = x + wproj @ attn_out + bproj
    mma_gemm<1><<<dim3(NN/128, CC/128, BB), 256, SM_GEMM_TOTAL>>>(wproj, p_ao, bproj, x, p_y1, CC, MIDD);
    // LN2
    ln_kernel<<<lnGrid, 256>>>(p_y1, ln2_g, ln2_b, p_ln);
    // hidden = gelu(w1 @ ln2 + b1)
    mma_gemm<2><<<dim3(NN/128, HIDD/128, BB), 256, SM_GEMM_TOTAL>>>(w1, p_ln, b1, nullptr, p_mid, HIDD, CC);
    // out = y1 + w2 @ hidden + b2
    mma_gemm<1><<<dim3(NN/128, CC/128, BB), 256, SM_GEMM_TOTAL>>>(w2, p_mid, b2, p_y1, out, CC, HIDD);
}

// round 5
// speedup vs baseline: 2.4649x; 1.5709x over previous
#include <cuda_runtime.h>
#include <cuda_bf16.h>
#include <cstdint>

// ---------------------------------------------------------------------------
// ViT block. B=16, C=384, N=1024 (32x32), NH=8, HD=48, MID=384, HID=1536.
// Layout [B, C, N] everywhere, fp32 in gmem.
// Projections AND attention on mma.sync m16n8k16 bf16 with 3-product hi/lo
// split (fp32-grade accuracy). tcgen05 unavailable (harness targets sm_100).
// ---------------------------------------------------------------------------

#define BB   16
#define CC   384
#define NN   1024
#define NHH  8
#define HDD  48
#define MIDD 384
#define HIDD 1536

// Scratch (device globals: allocation-free, graph-safe)
__device__ float g_ln [BB * CC   * NN];
__device__ float g_q  [BB * MIDD * NN];
__device__ float g_kv [BB * 2 * MIDD * NN];
__device__ float g_ao [BB * MIDD * NN];
__device__ float g_y1 [BB * CC   * NN];
__device__ float g_mid[BB * HIDD * NN];

__device__ __forceinline__ uint32_t smem_to_u32(const void* p) {
    uint32_t a;
    asm("{ .reg .u64 t; cvta.to.shared.u64 t, %1; cvt.u32.u64 %0, t; }" : "=r"(a) : "l"(p));
    return a;
}
__device__ __forceinline__ void ldmx4(uint32_t* r, uint32_t addr) {
    asm volatile("ldmatrix.sync.aligned.m8n8.x4.shared.b16 {%0,%1,%2,%3}, [%4];"
                 : "=r"(r[0]), "=r"(r[1]), "=r"(r[2]), "=r"(r[3]) : "r"(addr));
}
__device__ __forceinline__ void mma16816(float* c, const uint32_t* a,
                                         uint32_t b0, uint32_t b1) {
    asm volatile("mma.sync.aligned.m16n8k16.row.col.f32.bf16.bf16.f32 "
                 "{%0,%1,%2,%3}, {%4,%5,%6,%7}, {%8,%9}, {%0,%1,%2,%3};"
                 : "+f"(c[0]), "+f"(c[1]), "+f"(c[2]), "+f"(c[3])
                 : "r"(a[0]), "r"(a[1]), "r"(a[2]), "r"(a[3]), "r"(b0), "r"(b1));
}

union Pack16 { __nv_bfloat162 h2[4]; uint4 u; };

__device__ __forceinline__ void split8(const float* v, Pack16& hu, Pack16& lu) {
    #pragma unroll
    for (int j = 0; j < 4; j++) {
        __nv_bfloat16 h0 = __float2bfloat16(v[2*j]);
        __nv_bfloat16 h1 = __float2bfloat16(v[2*j+1]);
        __nv_bfloat16 l0 = __float2bfloat16(v[2*j]   - __bfloat162float(h0));
        __nv_bfloat16 l1 = __float2bfloat16(v[2*j+1] - __bfloat162float(h1));
        hu.h2[j] = __nv_bfloat162(h0, h1);
        lu.h2[j] = __nv_bfloat162(l0, l1);
    }
}

// ---------------------------------------------------------------------------
// LayerNorm over channel axis, per token, layout [B, C, N]. Coalesced in n.
// ---------------------------------------------------------------------------
__global__ __launch_bounds__(256)
void ln_kernel(const float* __restrict__ x, const float* __restrict__ g,
               const float* __restrict__ beta, float* __restrict__ out)
{
    const int b = blockIdx.y;
    const int n = blockIdx.x * 256 + threadIdx.x;
    const float* xp = x + (size_t)b * CC * NN + n;

    float sum = 0.f, sq = 0.f;
    #pragma unroll 4
    for (int c = 0; c < CC; c++) {
        float v = xp[(size_t)c * NN];
        sum += v; sq += v * v;
    }
    const float mean = sum * (1.f / CC);
    float var = sq * (1.f / CC) - mean * mean;
    var = var < 0.f ? 0.f : var;
    const float rstd = rsqrtf(var + 1e-5f);

    float* op = out + (size_t)b * CC * NN + n;
    #pragma unroll 4
    for (int c = 0; c < CC; c++) {
        float v = xp[(size_t)c * NN];
        op[(size_t)c * NN] = (v - mean) * rstd * g[c] + beta[c];
    }
}

// ---------------------------------------------------------------------------
// HMMA GEMM (unchanged from round 4): out = W @ Act (+bias/+res/+GELU)
// ---------------------------------------------------------------------------
#define TILE_HALF  (128 * 72)
#define SM_AHI 0
#define SM_ALO (TILE_HALF * 2)
#define SM_BHI (TILE_HALF * 4)
#define SM_BLO (TILE_HALF * 6)
#define SM_GEMM_TOTAL (TILE_HALF * 8)

template<int EPI>
__global__ __launch_bounds__(256, 2)
void mma_gemm(const float* __restrict__ W, const float* __restrict__ Act,
              const float* __restrict__ bias, const float* __restrict__ res,
              float* __restrict__ out, int O, int K)
{
    extern __shared__ __align__(16) char smem[];
    const uint32_t sbase = smem_to_u32(smem);

    const int b   = blockIdx.z;
    const int n0  = blockIdx.x * 128;
    const int o0  = blockIdx.y * 128;
    const int tid = threadIdx.x;
    const int wid = tid >> 5;
    const int lane = tid & 31;
    const int wm = wid & 1;
    const int wn = wid >> 1;

    float acc[4][4][4];
    #pragma unroll
    for (int i = 0; i < 4; i++)
        #pragma unroll
        for (int j = 0; j < 4; j++)
            #pragma unroll
            for (int e = 0; e < 4; e++) acc[i][j][e] = 0.f;

    const float* Ab = Act + (size_t)b * K * NN;

    const int a_row  = wm * 64 + (lane & 7) + (lane & 8);
    const int a_kg   = (lane >> 4);
    const int b_row  = wn * 32 + (lane & 7) + ((lane >> 4) & 1) * 8;
    const int b_kg   = (lane >> 3) & 1;

    const int nchunks = K >> 6;
    for (int chunk = 0; chunk < nchunks; chunk++) {
        const int k0 = chunk << 6;

        #pragma unroll
        for (int r = 0; r < 4; r++) {
            const int u = tid + 256 * r;
            const int t = u & 127;
            const int g = u >> 7;
            const float* ap = Ab + (size_t)(k0 + g * 8) * NN + n0 + t;
            float v[8];
            #pragma unroll
            for (int i = 0; i < 8; i++) v[i] = ap[(size_t)i * NN];
            Pack16 hu, lu; split8(v, hu, lu);
            const uint32_t off = (uint32_t)(t * 72 + g * 8) * 2;
            *(uint4*)(smem + SM_AHI + off) = hu.u;
            *(uint4*)(smem + SM_ALO + off) = lu.u;
        }
        #pragma unroll
        for (int r = 0; r < 4; r++) {
            const int u = tid + 256 * r;
            const int g = u & 7;
            const int row = u >> 3;
            const float4* wp = (const float4*)(W + (size_t)(o0 + row) * K + k0 + g * 8);
            const float4 w0 = wp[0], w1 = wp[1];
            float v[8] = {w0.x, w0.y, w0.z, w0.w, w1.x, w1.y, w1.z, w1.w};
            Pack16 hu, lu; split8(v, hu, lu);
            const uint32_t off = (uint32_t)(row * 72 + g * 8) * 2;
            *(uint4*)(smem + SM_BHI + off) = hu.u;
            *(uint4*)(smem + SM_BLO + off) = lu.u;
        }
        __syncthreads();

        #pragma unroll
        for (int ks = 0; ks < 4; ks++) {
            uint32_t bh[8], bl[8];
            #pragma unroll
            for (int ng = 0; ng < 2; ng++) {
                const uint32_t boff =
                    (uint32_t)((b_row + ng * 16) * 72 + (ks * 2 + b_kg) * 8) * 2;
                ldmx4(&bh[ng * 4], sbase + SM_BHI + boff);
                ldmx4(&bl[ng * 4], sbase + SM_BLO + boff);
            }
            #pragma unroll
            for (int mf = 0; mf < 4; mf++) {
                const uint32_t aoff =
                    (uint32_t)((a_row + mf * 16) * 72 + (ks * 2 + a_kg) * 8) * 2;
                uint32_t ah[4], al[4];
                ldmx4(ah, sbase + SM_AHI + aoff);
                ldmx4(al, sbase + SM_ALO + aoff);
                #pragma unroll
                for (int nf = 0; nf < 4; nf++) {
                    const int bi = (nf >> 1) * 4 + (nf & 1) * 2;
                    mma16816(acc[mf][nf], ah, bh[bi], bh[bi + 1]);
                    mma16816(acc[mf][nf], ah, bl[bi], bl[bi + 1]);
                    mma16816(acc[mf][nf], al, bh[bi], bh[bi + 1]);
                }
            }
        }
        __syncthreads();
    }

    float* Cs = (float*)smem;  // [128 o][132 m]
    #pragma unroll
    for (int mf = 0; mf < 4; mf++) {
        const int m = wm * 64 + mf * 16 + (lane >> 2);
        #pragma unroll
        for (int nf = 0; nf < 4; nf++) {
            const int ol = wn * 32 + nf * 8 + (lane & 3) * 2;
            Cs[ ol      * 132 + m    ] = acc[mf][nf][0];
            Cs[(ol + 1) * 132 + m    ] = acc[mf][nf][1];
            Cs[ ol      * 132 + m + 8] = acc[mf][nf][2];
            Cs[(ol + 1) * 132 + m + 8] = acc[mf][nf][3];
        }
    }
    __syncthreads();

    #pragma unroll 4
    for (int i = 0; i < 64; i++) {
        const int idx = tid + 256 * i;
        const int ol = idx >> 7;
        const int m  = idx & 127;
        const int o  = o0 + ol;
        float v = Cs[ol * 132 + m] + bias[o];
        const size_t gidx = ((size_t)b * O + o) * NN + n0 + m;
        if (EPI == 1) v += res[gidx];
        if (EPI == 2) v = 0.5f * v * (1.f + erff(v * 0.7071067811865476f));
        out[gidx] = v;
    }
}

// ---------------------------------------------------------------------------
// MMA flash attention. Grid (8 qblocks, NH, B), 256 threads = 8 warps.
// Warp w owns q rows [qb*128 + w*16, +16). K tile [128k][48d] hi/lo bf16;
// V^T tile [48d][128k] hi/lo (natural gmem orientation). Q frags in regs.
// Online softmax on S fragments; P repacked c-frag -> a-frag (no smem).
// 3-product split on both GEMMs. Bias from algebraic 35x63 SMEM window.
// ---------------------------------------------------------------------------
#define AT_KHI  0
#define AT_KLO  14336                  // 128*56*2
#define AT_VHI  28672
#define AT_VLO  41728                  // 48*136*2 = 13056
#define AT_BIAS 54784
#define AT_TOTAL (54784 + 35 * 64 * 4) // 63744 B

__global__ __launch_bounds__(256)
void attn_kernel(const float* __restrict__ q, const float* __restrict__ kv,
                 const float* __restrict__ rpb, float* __restrict__ o)
{
    extern __shared__ __align__(16) char smem[];
    const uint32_t sb = smem_to_u32(smem);
    const int tid = threadIdx.x, lane = tid & 31, w = tid >> 5;
    const int qb = blockIdx.x, h = blockIdx.y, b = blockIdx.z;

    float* bias_s = (float*)(smem + AT_BIAS);
    for (int e = tid; e < 35 * 63; e += 256) {
        const int a = e / 63, dw = e % 63;
        bias_s[a * 64 + dw] = rpb[((size_t)((a + qb * 4) * 63 + dw)) * NHH + h];
    }

    const float* qp = q + ((size_t)(b * MIDD + h * HDD)) * NN + qb * 128;
    const float* kp = kv + ((size_t)(b * 2 * MIDD + h * HDD)) * NN;
    const float* vp = kp + (size_t)MIDD * NN;

    // ---- stage scaled Q (transposed, split) into the K buffers ----
    #pragma unroll
    for (int r = 0; r < 3; r++) {
        const int u = tid + 256 * r;
        const int t = u & 127, g = u >> 7;
        const float* ap = qp + (size_t)(g * 8) * NN + t;
        float v[8];
        #pragma unroll
        for (int i = 0; i < 8; i++) v[i] = ap[(size_t)i * NN] * 0.14433756729740643f;
        Pack16 hu, lu; split8(v, hu, lu);
        const uint32_t off = (uint32_t)(t * 56 + g * 8) * 2;
        *(uint4*)(smem + AT_KHI + off) = hu.u;
        *(uint4*)(smem + AT_KLO + off) = lu.u;
    }
    __syncthreads();

    // ---- Q fragments -> registers (live whole kernel) ----
    uint32_t qh[3][4], ql[3][4];
    {
        const int row = w * 16 + (lane & 15);
        #pragma unroll
        for (int ks = 0; ks < 3; ks++) {
            const uint32_t off = (uint32_t)(row * 56 + ks * 16 + (lane >> 4) * 8) * 2;
            ldmx4(qh[ks], sb + AT_KHI + off);
            ldmx4(ql[ks], sb + AT_KLO + off);
        }
    }

    float of[6][4];
    #pragma unroll
    for (int i = 0; i < 6; i++)
        #pragma unroll
        for (int e = 0; e < 4; e++) of[i][e] = 0.f;
    float mrow0 = -1e30f, mrow1 = -1e30f, lrow0 = 0.f, lrow1 = 0.f;

    const int trow0 = w * 16 + (lane >> 2);     // rows for c0/c1
    const int hn0 = trow0 >> 5, wn0 = trow0 & 31;
    const int trow1 = trow0 + 8;                 // rows for c2/c3
    const int hn1 = trow1 >> 5, wn1 = trow1 & 31;

    for (int kb = 0; kb < 8; kb++) {
        __syncthreads();
        // K tile [128 keys][48 d] (transpose in load map, coalesced over keys)
        #pragma unroll
        for (int r = 0; r < 3; r++) {
            const int u = tid + 256 * r;
            const int t = u & 127, g = u >> 7;
            const float* ap = kp + (size_t)(g * 8) * NN + kb * 128 + t;
            float v[8];
            #pragma unroll
            for (int i = 0; i < 8; i++) v[i] = ap[(size_t)i * NN];
            Pack16 hu, lu; split8(v, hu, lu);
            const uint32_t off = (uint32_t)(t * 56 + g * 8) * 2;
            *(uint4*)(smem + AT_KHI + off) = hu.u;
            *(uint4*)(smem + AT_KLO + off) = lu.u;
        }
        // V^T tile [48 d][128 keys] (natural orientation: contiguous keys)
        #pragma unroll
        for (int r = 0; r < 3; r++) {
            const int u = tid + 256 * r;
            const int g = u & 15, d = u >> 4;
            const float4* ap = (const float4*)(vp + (size_t)d * NN + kb * 128 + g * 8);
            const float4 v0 = ap[0], v1 = ap[1];
            float v[8] = {v0.x, v0.y, v0.z, v0.w, v1.x, v1.y, v1.z, v1.w};
            Pack16 hu, lu; split8(v, hu, lu);
            const uint32_t off = (uint32_t)(d * 136 + g * 8) * 2;
            *(uint4*)(smem + AT_VHI + off) = hu.u;
            *(uint4*)(smem + AT_VLO + off) = lu.u;
        }
        __syncthreads();

        // ---- S = Q K^T (16 nfrags of 16x8 over 128 keys) ----
        float s[16][4];
        #pragma unroll
        for (int i = 0; i < 16; i++)
            #pragma unroll
            for (int e = 0; e < 4; e++) s[i][e] = 0.f;

        #pragma unroll
        for (int ks = 0; ks < 3; ks++) {
            #pragma unroll
            for (int np = 0; np < 8; np++) {
                const int krow = np * 16 + (lane & 7) + ((lane & 16) ? 8 : 0);
                const int kcol = ks * 16 + ((lane & 8) ? 8 : 0);
                const uint32_t off = (uint32_t)(krow * 56 + kcol) * 2;
                uint32_t kh4[4], kl4[4];
                ldmx4(kh4, sb + AT_KHI + off);
                ldmx4(kl4, sb + AT_KLO + off);
                mma16816(s[2*np],   qh[ks], kh4[0], kh4[1]);
                mma16816(s[2*np],   qh[ks], kl4[0], kl4[1]);
                mma16816(s[2*np],   ql[ks], kh4[0], kh4[1]);
                mma16816(s[2*np+1], qh[ks], kh4[2], kh4[3]);
                mma16816(s[2*np+1], qh[ks], kl4[2], kl4[3]);
                mma16816(s[2*np+1], ql[ks], kh4[2], kh4[3]);
            }
        }

        // ---- rel-pos bias + online softmax ----
        float mx0 = -1e30f, mx1 = -1e30f;
        #pragma unroll
        for (int nf = 0; nf < 16; nf++) {
            const int j0 = nf * 8 + (lane & 3) * 2;   // even => j0,j0+1 share hm
            const int hm = kb * 4 + (j0 >> 5);
            const int wm = j0 & 31;
            const float* br0 = bias_s + (hn0 + 31 - hm) * 64 + (wn0 - wm + 31);
            const float* br1 = bias_s + (hn1 + 31 - hm) * 64 + (wn1 - wm + 31);
            s[nf][0] += br0[0];
            s[nf][1] += br0[-1];
            s[nf][2] += br1[0];
            s[nf][3] += br1[-1];
            mx0 = fmaxf(mx0, fmaxf(s[nf][0], s[nf][1]));
            mx1 = fmaxf(mx1, fmaxf(s[nf][2], s[nf][3]));
        }
        mx0 = fmaxf(mx0, __shfl_xor_sync(0xffffffffu, mx0, 1));
        mx0 = fmaxf(mx0, __shfl_xor_sync(0xffffffffu, mx0, 2));
        mx1 = fmaxf(mx1, __shfl_xor_sync(0xffffffffu, mx1, 1));
        mx1 = fmaxf(mx1, __shfl_xor_sync(0xffffffffu, mx1, 2));
        const float mn0 = fmaxf(mrow0, mx0), mn1 = fmaxf(mrow1, mx1);
        const float c0 = __expf(mrow0 - mn0), c1 = __expf(mrow1 - mn1);
        mrow0 = mn0; mrow1 = mn1;
        #pragma unroll
        for (int nf = 0; nf < 6; nf++) {
            of[nf][0] *= c0; of[nf][1] *= c0;
            of[nf][2] *= c1; of[nf][3] *= c1;
        }
        float sum0 = 0.f, sum1 = 0.f;
        #pragma unroll
        for (int nf = 0; nf < 16; nf++) {
            s[nf][0] = __expf(s[nf][0] - mn0); sum0 += s[nf][0];
            s[nf][1] = __expf(s[nf][1] - mn0); sum0 += s[nf][1];
            s[nf][2] = __expf(s[nf][2] - mn1); sum1 += s[nf][2];
            s[nf][3] = __expf(s[nf][3] - mn1); sum1 += s[nf][3];
        }
        sum0 += __shfl_xor_sync(0xffffffffu, sum0, 1);
        sum0 += __shfl_xor_sync(0xffffffffu, sum0, 2);
        sum1 += __shfl_xor_sync(0xffffffffu, sum1, 1);
        sum1 += __shfl_xor_sync(0xffffffffu, sum1, 2);
        lrow0 = lrow0 * c0 + sum0;
        lrow1 = lrow1 * c1 + sum1;

        // ---- O += P V : P c-frags repacked as a-frags, split hi/lo ----
        #pragma unroll
        for (int ks = 0; ks < 8; ks++) {
            uint32_t ah[4], al[4];
            {
                const float f[8] = {s[2*ks][0],   s[2*ks][1],   s[2*ks][2],   s[2*ks][3],
                                    s[2*ks+1][0], s[2*ks+1][1], s[2*ks+1][2], s[2*ks+1][3]};
                #pragma unroll
                for (int i = 0; i < 4; i++) {
                    __nv_bfloat16 h0 = __float2bfloat16(f[2*i]);
                    __nv_bfloat16 h1 = __float2bfloat16(f[2*i+1]);
                    __nv_bfloat16 l0 = __float2bfloat16(f[2*i]   - __bfloat162float(h0));
                    __nv_bfloat16 l1 = __float2bfloat16(f[2*i+1] - __bfloat162float(h1));
                    __nv_bfloat162 hh(h0, h1), ll(l0, l1);
                    ah[i] = *(uint32_t*)&hh;
                    al[i] = *(uint32_t*)&ll;
                }
            }
            #pragma unroll
            for (int np = 0; np < 3; np++) {
                const int drow = np * 16 + (lane & 7) + ((lane & 16) ? 8 : 0);
                const int kc = ks * 16 + ((lane & 8) ? 8 : 0);
                const uint32_t off = (uint32_t)(drow * 136 + kc) * 2;
                uint32_t vh4[4], vl4[4];
                ldmx4(vh4, sb + AT_VHI + off);
                ldmx4(vl4, sb + AT_VLO + off);
                mma16816(of[2*np],   ah, vh4[0], vh4[1]);
                mma16816(of[2*np],   ah, vl4[0], vl4[1]);
                mma16816(of[2*np],   al, vh4[0], vh4[1]);
                mma16816(of[2*np+1], ah, vh4[2], vh4[3]);
                mma16816(of[2*np+1], ah, vl4[2], vl4[3]);
                mma16816(of[2*np+1], al, vh4[2], vh4[3]);
            }
        }
    }

    // ---- normalize + transpose via smem + coalesced store ----
    const float inv0 = 1.f / lrow0, inv1 = 1.f / lrow1;
    __syncthreads();
    float* Os = (float*)smem;   // [48 d][132]
    #pragma unroll
    for (int nf = 0; nf < 6; nf++) {
        const int d0 = nf * 8 + (lane & 3) * 2;
        const int t0 = w * 16 + (lane >> 2);
        Os[ d0      * 132 + t0    ] = of[nf][0] * inv0;
        Os[(d0 + 1) * 132 + t0    ] = of[nf][1] * inv0;
        Os[ d0      * 132 + t0 + 8] = of[nf][2] * inv1;
        Os[(d0 + 1) * 132 + t0 + 8] = of[nf][3] * inv1;
    }
    __syncthreads();
    float* op = o + ((size_t)(b * MIDD + h * HDD)) * NN + qb * 128;
    #pragma unroll
    for (int i = 0; i < 24; i++) {
        const int u = tid + 256 * i;
        const int d = u >> 7, t = u & 127;
        op[(size_t)d * NN + t] = Os[d * 132 + t];
    }
}

// ---------------------------------------------------------------------------
// Launch sequence (kernel launches only: graph-capturable)
// ---------------------------------------------------------------------------
extern "C" void kernel_launch(void* const* d_in, const int* in_sizes, int n_in,
                              void* d_out, int out_size)
{
    const float* x     = (const float*)d_in[0];
    const float* rpb   = (const float*)d_in[1];
    const float* ln1_g = (const float*)d_in[3];
    const float* ln1_b = (const float*)d_in[4];
    const float* ln2_g = (const float*)d_in[5];
    const float* ln2_b = (const float*)d_in[6];
    const float* wq    = (const float*)d_in[7];
    const float* bq    = (const float*)d_in[8];
    const float* wkv   = (const float*)d_in[9];
    const float* bkv   = (const float*)d_in[10];
    const float* wproj = (const float*)d_in[11];
    const float* bproj = (const float*)d_in[12];
    const float* w1    = (const float*)d_in[13];
    const float* b1    = (const float*)d_in[14];
    const float* w2    = (const float*)d_in[15];
    const float* b2    = (const float*)d_in[16];
    float* out = (float*)d_out;

    float *p_ln, *p_q, *p_kv, *p_ao, *p_y1, *p_mid;
    cudaGetSymbolAddress((void**)&p_ln,  g_ln);
    cudaGetSymbolAddress((void**)&p_q,   g_q);
    cudaGetSymbolAddress((void**)&p_kv,  g_kv);
    cudaGetSymbolAddress((void**)&p_ao,  g_ao);
    cudaGetSymbolAddress((void**)&p_y1,  g_y1);
    cudaGetSymbolAddress((void**)&p_mid, g_mid);

    cudaFuncSetAttribute(mma_gemm<0>, cudaFuncAttributeMaxDynamicSharedMemorySize, SM_GEMM_TOTAL);
    cudaFuncSetAttribute(mma_gemm<1>, cudaFuncAttributeMaxDynamicSharedMemorySize, SM_GEMM_TOTAL);
    cudaFuncSetAttribute(mma_gemm<2>, cudaFuncAttributeMaxDynamicSharedMemorySize, SM_GEMM_TOTAL);
    cudaFuncSetAttribute(attn_kernel, cudaFuncAttributeMaxDynamicSharedMemorySize, AT_TOTAL);

    const dim3 lnGrid(NN / 256, BB);

    // LN1
    ln_kernel<<<lnGrid, 256>>>(x, ln1_g, ln1_b, p_ln);
    // Q = wq @ ln1 + bq
    mma_gemm<0><<<dim3(NN/128, MIDD/128,   BB), 256, SM_GEMM_TOTAL>>>(wq,  p_ln, bq,  nullptr, p_q,  MIDD,   CC);
    // KV = wkv @ ln1 + bkv
    mma_gemm<0><<<dim3(NN/128, 2*MIDD/128, BB), 256, SM_GEMM_TOTAL>>>(wkv, p_ln, bkv, nullptr, p_kv, 2*MIDD, CC);
    // Attention (MMA flash)
    attn_kernel<<<dim3(NN/128, NHH, BB), 256, AT_TOTAL>>>(p_q, p_kv, rpb, p_ao);
    // y1 = x + wproj @ attn_out + bproj
    mma_gemm<1><<<dim3(NN/128, CC/128, BB), 256, SM_GEMM_TOTAL>>>(wproj, p_ao, bproj, x, p_y1, CC, MIDD);
    // LN2
    ln_kernel<<<lnGrid, 256>>>(p_y1, ln2_g, ln2_b, p_ln);
    // hidden = gelu(w1 @ ln2 + b1)
    mma_gemm<2><<<dim3(NN/128, HIDD/128, BB), 256, SM_GEMM_TOTAL>>>(w1, p_ln, b1, nullptr, p_mid, HIDD, CC);
    // out = y1 + w2 @ hidden + b2
    mma_gemm<1><<<dim3(NN/128, CC/128, BB), 256, SM_GEMM_TOTAL>>>(w2, p_mid, b2, p_y1, out, CC, HIDD);
}

// round 6
// speedup vs baseline: 2.5202x; 1.0224x over previous
#include <cuda_runtime.h>
#include <cuda_bf16.h>
#include <cstdint>

// ---------------------------------------------------------------------------
// ViT block. B=16, C=384, N=1024 (32x32), NH=8, HD=48, MID=384, HID=1536.
// fp32 I/O; internal activations stored as packed (hi,lo) bf16 pairs in one
// uint32 (hi = bits[0:16], lo = bits[16:32]) -> 3-product split MMA with zero
// conversion cost in hot loops. Weights pre-split per launch into hi/lo planes.
// All matmuls on mma.sync m16n8k16 bf16 (tcgen05 unavailable: target sm_100).
// ---------------------------------------------------------------------------

#define BB   16
#define CC   384
#define NN   1024
#define NHH  8
#define HDD  48
#define MIDD 384
#define HIDD 1536

// Scratch (device globals: allocation-free, graph-safe)
__device__ uint32_t g_lnp[BB * CC   * NN];     // packed LN output (LN1/LN2)
__device__ uint32_t g_q  [BB * MIDD * NN];     // packed
__device__ uint32_t g_kv [BB * 2 * MIDD * NN]; // packed
__device__ uint32_t g_ao [BB * MIDD * NN];     // packed
__device__ float    g_y1 [BB * CC   * NN];     // fp32 (residual)
__device__ uint32_t g_mid[BB * HIDD * NN];     // packed
// Split weight planes (concatenated): q | kv | proj | w1 | w2
#define WOFF_Q    0
#define WOFF_KV   147456
#define WOFF_PROJ 442368
#define WOFF_W1   589824
#define WOFF_W2   1179648
#define WTOTAL    1769472
__device__ __nv_bfloat16 g_wh[WTOTAL];
__device__ __nv_bfloat16 g_wl[WTOTAL];

__device__ __forceinline__ uint32_t smem_to_u32(const void* p) {
    uint32_t a;
    asm("{ .reg .u64 t; cvta.to.shared.u64 t, %1; cvt.u32.u64 %0, t; }" : "=r"(a) : "l"(p));
    return a;
}
__device__ __forceinline__ void ldmx4(uint32_t* r, uint32_t addr) {
    asm volatile("ldmatrix.sync.aligned.m8n8.x4.shared.b16 {%0,%1,%2,%3}, [%4];"
                 : "=r"(r[0]), "=r"(r[1]), "=r"(r[2]), "=r"(r[3]) : "r"(addr));
}
__device__ __forceinline__ void mma16816(float* c, const uint32_t* a,
                                         uint32_t b0, uint32_t b1) {
    asm volatile("mma.sync.aligned.m16n8k16.row.col.f32.bf16.bf16.f32 "
                 "{%0,%1,%2,%3}, {%4,%5,%6,%7}, {%8,%9}, {%0,%1,%2,%3};"
                 : "+f"(c[0]), "+f"(c[1]), "+f"(c[2]), "+f"(c[3])
                 : "r"(a[0]), "r"(a[1]), "r"(a[2]), "r"(a[3]), "r"(b0), "r"(b1));
}
// pack fp32 -> (hi,lo) bf16 pair in one uint32
__device__ __forceinline__ uint32_t packsplit(float v) {
    __nv_bfloat16 h = __float2bfloat16(v);
    __nv_bfloat16 l = __float2bfloat16(v - __bfloat162float(h));
    __nv_bfloat162 t(h, l);
    return *(uint32_t*)&t;
}
// combine two packed values -> (hi0,hi1) and (lo0,lo1)
#define HI_PAIR(u0, u1) __byte_perm((u0), (u1), 0x5410)
#define LO_PAIR(u0, u1) __byte_perm((u0), (u1), 0x7632)

// ---------------------------------------------------------------------------
// Weight split: w -> hi/lo bf16 planes
// ---------------------------------------------------------------------------
__global__ __launch_bounds__(256)
void wconv_kernel(const float* __restrict__ w, __nv_bfloat16* __restrict__ wh,
                  __nv_bfloat16* __restrict__ wl, int n)
{
    const int i = blockIdx.x * 256 + threadIdx.x;
    if (i < n) {
        const float v = w[i];
        const __nv_bfloat16 h = __float2bfloat16(v);
        wh[i] = h;
        wl[i] = __float2bfloat16(v - __bfloat162float(h));
    }
}

// ---------------------------------------------------------------------------
// LayerNorm over channels -> packed hi/lo output. Coalesced in n.
// ---------------------------------------------------------------------------
__global__ __launch_bounds__(256)
void ln_kernel(const float* __restrict__ x, const float* __restrict__ g,
               const float* __restrict__ beta, uint32_t* __restrict__ out)
{
    const int b = blockIdx.y;
    const int n = blockIdx.x * 256 + threadIdx.x;
    const float* xp = x + (size_t)b * CC * NN + n;

    float sum = 0.f, sq = 0.f;
    #pragma unroll 4
    for (int c = 0; c < CC; c++) {
        float v = xp[(size_t)c * NN];
        sum += v; sq += v * v;
    }
    const float mean = sum * (1.f / CC);
    float var = sq * (1.f / CC) - mean * mean;
    var = var < 0.f ? 0.f : var;
    const float rstd = rsqrtf(var + 1e-5f);

    uint32_t* op = out + (size_t)b * CC * NN + n;
    #pragma unroll 4
    for (int c = 0; c < CC; c++) {
        float v = xp[(size_t)c * NN];
        op[(size_t)c * NN] = packsplit((v - mean) * rstd * g[c] + beta[c]);
    }
}

// ---------------------------------------------------------------------------
// HMMA GEMM: out[b][o][n] = sum_c W[o][c]*Act[b][c][n] (+bias, +epilogue)
// A from packed activations, B from pre-split weight planes.
// CTA 128x128, K-chunk 64, 8 warps 2x4, warp tile 64x32, rows padded to 72.
// EPI: 1 = fp32 out + residual; 3 = packed out; 4 = GELU + packed out.
// ---------------------------------------------------------------------------
#define TILE_HALF  (128 * 72)
#define SM_AHI 0
#define SM_ALO (TILE_HALF * 2)
#define SM_BHI (TILE_HALF * 4)
#define SM_BLO (TILE_HALF * 6)
#define SM_GEMM_TOTAL (TILE_HALF * 8)

template<int EPI>
__global__ __launch_bounds__(256, 2)
void mma_gemm(const __nv_bfloat16* __restrict__ Wh, const __nv_bfloat16* __restrict__ Wl,
              const uint32_t* __restrict__ Act, const float* __restrict__ bias,
              const float* __restrict__ res, void* __restrict__ outv, int O, int K)
{
    extern __shared__ __align__(16) char smem[];
    const uint32_t sbase = smem_to_u32(smem);

    const int b   = blockIdx.z;
    const int n0  = blockIdx.x * 128;
    const int o0  = blockIdx.y * 128;
    const int tid = threadIdx.x;
    const int wid = tid >> 5;
    const int lane = tid & 31;
    const int wm = wid & 1;
    const int wn = wid >> 1;

    float acc[4][4][4];
    #pragma unroll
    for (int i = 0; i < 4; i++)
        #pragma unroll
        for (int j = 0; j < 4; j++)
            #pragma unroll
            for (int e = 0; e < 4; e++) acc[i][j][e] = 0.f;

    const uint32_t* Ab = Act + (size_t)b * K * NN;

    const int a_row  = wm * 64 + (lane & 7) + (lane & 8);
    const int a_kg   = (lane >> 4);
    const int b_row  = wn * 32 + (lane & 7) + ((lane >> 4) & 1) * 8;
    const int b_kg   = (lane >> 3) & 1;

    const int nchunks = K >> 6;
    for (int chunk = 0; chunk < nchunks; chunk++) {
        const int k0 = chunk << 6;

        // A tile: packed loads (lanes sweep tokens: coalesced) + PRMT split
        #pragma unroll
        for (int r = 0; r < 4; r++) {
            const int u = tid + 256 * r;
            const int t = u & 127;
            const int g = u >> 7;
            const uint32_t* ap = Ab + (size_t)(k0 + g * 8) * NN + n0 + t;
            uint32_t p[8];
            #pragma unroll
            for (int i = 0; i < 8; i++) p[i] = ap[(size_t)i * NN];
            uint4 hu, lu;
            hu.x = HI_PAIR(p[0], p[1]); lu.x = LO_PAIR(p[0], p[1]);
            hu.y = HI_PAIR(p[2], p[3]); lu.y = LO_PAIR(p[2], p[3]);
            hu.z = HI_PAIR(p[4], p[5]); lu.z = LO_PAIR(p[4], p[5]);
            hu.w = HI_PAIR(p[6], p[7]); lu.w = LO_PAIR(p[6], p[7]);
            const uint32_t off = (uint32_t)(t * 72 + g * 8) * 2;
            *(uint4*)(smem + SM_AHI + off) = hu;
            *(uint4*)(smem + SM_ALO + off) = lu;
        }
        // B tile: raw plane copies (contiguous along k: coalesced)
        #pragma unroll
        for (int r = 0; r < 4; r++) {
            const int u = tid + 256 * r;
            const int g = u & 7;
            const int row = u >> 3;
            const size_t widx = (size_t)(o0 + row) * K + k0 + g * 8;
            const uint32_t off = (uint32_t)(row * 72 + g * 8) * 2;
            *(uint4*)(smem + SM_BHI + off) = *(const uint4*)(Wh + widx);
            *(uint4*)(smem + SM_BLO + off) = *(const uint4*)(Wl + widx);
        }
        __syncthreads();

        #pragma unroll
        for (int ks = 0; ks < 4; ks++) {
            uint32_t bh[8], bl[8];
            #pragma unroll
            for (int ng = 0; ng < 2; ng++) {
                const uint32_t boff =
                    (uint32_t)((b_row + ng * 16) * 72 + (ks * 2 + b_kg) * 8) * 2;
                ldmx4(&bh[ng * 4], sbase + SM_BHI + boff);
                ldmx4(&bl[ng * 4], sbase + SM_BLO + boff);
            }
            #pragma unroll
            for (int mf = 0; mf < 4; mf++) {
                const uint32_t aoff =
                    (uint32_t)((a_row + mf * 16) * 72 + (ks * 2 + a_kg) * 8) * 2;
                uint32_t ah[4], al[4];
                ldmx4(ah, sbase + SM_AHI + aoff);
                ldmx4(al, sbase + SM_ALO + aoff);
                #pragma unroll
                for (int nf = 0; nf < 4; nf++) {
                    const int bi = (nf >> 1) * 4 + (nf & 1) * 2;
                    mma16816(acc[mf][nf], ah, bh[bi], bh[bi + 1]);
                    mma16816(acc[mf][nf], ah, bl[bi], bl[bi + 1]);
                    mma16816(acc[mf][nf], al, bh[bi], bh[bi + 1]);
                }
            }
        }
        __syncthreads();
    }

    // Epilogue: transpose via smem, coalesced gmem writes
    float* Cs = (float*)smem;  // [128 o][132 m]
    #pragma unroll
    for (int mf = 0; mf < 4; mf++) {
        const int m = wm * 64 + mf * 16 + (lane >> 2);
        #pragma unroll
        for (int nf = 0; nf < 4; nf++) {
            const int ol = wn * 32 + nf * 8 + (lane & 3) * 2;
            Cs[ ol      * 132 + m    ] = acc[mf][nf][0];
            Cs[(ol + 1) * 132 + m    ] = acc[mf][nf][1];
            Cs[ ol      * 132 + m + 8] = acc[mf][nf][2];
            Cs[(ol + 1) * 132 + m + 8] = acc[mf][nf][3];
        }
    }
    __syncthreads();

    #pragma unroll 4
    for (int i = 0; i < 64; i++) {
        const int idx = tid + 256 * i;
        const int ol = idx >> 7;
        const int m  = idx & 127;
        const int o  = o0 + ol;
        float v = Cs[ol * 132 + m] + bias[o];
        const size_t gidx = ((size_t)b * O + o) * NN + n0 + m;
        if (EPI == 1) {
            ((float*)outv)[gidx] = v + res[gidx];
        } else {
            if (EPI == 4) v = 0.5f * v * (1.f + erff(v * 0.7071067811865476f));
            ((uint32_t*)outv)[gidx] = packsplit(v);
        }
    }
}

// ---------------------------------------------------------------------------
// MMA flash attention (packed inputs/outputs). Grid (8, NH, B), 256 threads.
// Scale folded into the bias-add FMA. Structure as round 5.
// ---------------------------------------------------------------------------
#define AT_KHI  0
#define AT_KLO  14336
#define AT_VHI  28672
#define AT_VLO  41728
#define AT_BIAS 54784
#define AT_TOTAL (54784 + 35 * 64 * 4)
#define ATT_SCALE 0.14433756729740643f

__global__ __launch_bounds__(256)
void attn_kernel(const uint32_t* __restrict__ q, const uint32_t* __restrict__ kv,
                 const float* __restrict__ rpb, uint32_t* __restrict__ o)
{
    extern __shared__ __align__(16) char smem[];
    const uint32_t sb = smem_to_u32(smem);
    const int tid = threadIdx.x, lane = tid & 31, w = tid >> 5;
    const int qb = blockIdx.x, h = blockIdx.y, b = blockIdx.z;

    float* bias_s = (float*)(smem + AT_BIAS);
    for (int e = tid; e < 35 * 63; e += 256) {
        const int a = e / 63, dw = e % 63;
        bias_s[a * 64 + dw] = rpb[((size_t)((a + qb * 4) * 63 + dw)) * NHH + h];
    }

    const uint32_t* qp = q + ((size_t)(b * MIDD + h * HDD)) * NN + qb * 128;
    const uint32_t* kp = kv + ((size_t)(b * 2 * MIDD + h * HDD)) * NN;
    const uint32_t* vp = kp + (size_t)MIDD * NN;

    // stage Q (transposed) into K buffers
    #pragma unroll
    for (int r = 0; r < 3; r++) {
        const int u = tid + 256 * r;
        const int t = u & 127, g = u >> 7;
        const uint32_t* ap = qp + (size_t)(g * 8) * NN + t;
        uint32_t p[8];
        #pragma unroll
        for (int i = 0; i < 8; i++) p[i] = ap[(size_t)i * NN];
        uint4 hu, lu;
        hu.x = HI_PAIR(p[0], p[1]); lu.x = LO_PAIR(p[0], p[1]);
        hu.y = HI_PAIR(p[2], p[3]); lu.y = LO_PAIR(p[2], p[3]);
        hu.z = HI_PAIR(p[4], p[5]); lu.z = LO_PAIR(p[4], p[5]);
        hu.w = HI_PAIR(p[6], p[7]); lu.w = LO_PAIR(p[6], p[7]);
        const uint32_t off = (uint32_t)(t * 56 + g * 8) * 2;
        *(uint4*)(smem + AT_KHI + off) = hu;
        *(uint4*)(smem + AT_KLO + off) = lu;
    }
    __syncthreads();

    uint32_t qh[3][4], ql[3][4];
    {
        const int row = w * 16 + (lane & 15);
        #pragma unroll
        for (int ks = 0; ks < 3; ks++) {
            const uint32_t off = (uint32_t)(row * 56 + ks * 16 + (lane >> 4) * 8) * 2;
            ldmx4(qh[ks], sb + AT_KHI + off);
            ldmx4(ql[ks], sb + AT_KLO + off);
        }
    }

    float of[6][4];
    #pragma unroll
    for (int i = 0; i < 6; i++)
        #pragma unroll
        for (int e = 0; e < 4; e++) of[i][e] = 0.f;
    float mrow0 = -1e30f, mrow1 = -1e30f, lrow0 = 0.f, lrow1 = 0.f;

    const int trow0 = w * 16 + (lane >> 2);
    const int hn0 = trow0 >> 5, wn0 = trow0 & 31;
    const int trow1 = trow0 + 8;
    const int hn1 = trow1 >> 5, wn1 = trow1 & 31;

    for (int kb = 0; kb < 8; kb++) {
        __syncthreads();
        // K tile [128k][48d]
        #pragma unroll
        for (int r = 0; r < 3; r++) {
            const int u = tid + 256 * r;
            const int t = u & 127, g = u >> 7;
            const uint32_t* ap = kp + (size_t)(g * 8) * NN + kb * 128 + t;
            uint32_t p[8];
            #pragma unroll
            for (int i = 0; i < 8; i++) p[i] = ap[(size_t)i * NN];
            uint4 hu, lu;
            hu.x = HI_PAIR(p[0], p[1]); lu.x = LO_PAIR(p[0], p[1]);
            hu.y = HI_PAIR(p[2], p[3]); lu.y = LO_PAIR(p[2], p[3]);
            hu.z = HI_PAIR(p[4], p[5]); lu.z = LO_PAIR(p[4], p[5]);
            hu.w = HI_PAIR(p[6], p[7]); lu.w = LO_PAIR(p[6], p[7]);
            const uint32_t off = (uint32_t)(t * 56 + g * 8) * 2;
            *(uint4*)(smem + AT_KHI + off) = hu;
            *(uint4*)(smem + AT_KLO + off) = lu;
        }
        // V^T tile [48d][128k] (contiguous packed loads)
        #pragma unroll
        for (int r = 0; r < 3; r++) {
            const int u = tid + 256 * r;
            const int g = u & 15, d = u >> 4;
            const uint4* ap = (const uint4*)(vp + (size_t)d * NN + kb * 128 + g * 8);
            const uint4 p0 = ap[0], p1 = ap[1];
            uint4 hu, lu;
            hu.x = HI_PAIR(p0.x, p0.y); lu.x = LO_PAIR(p0.x, p0.y);
            hu.y = HI_PAIR(p0.z, p0.w); lu.y = LO_PAIR(p0.z, p0.w);
            hu.z = HI_PAIR(p1.x, p1.y); lu.z = LO_PAIR(p1.x, p1.y);
            hu.w = HI_PAIR(p1.z, p1.w); lu.w = LO_PAIR(p1.z, p1.w);
            const uint32_t off = (uint32_t)(d * 136 + g * 8) * 2;
            *(uint4*)(smem + AT_VHI + off) = hu;
            *(uint4*)(smem + AT_VLO + off) = lu;
        }
        __syncthreads();

        // S = Q K^T
        float s[16][4];
        #pragma unroll
        for (int i = 0; i < 16; i++)
            #pragma unroll
            for (int e = 0; e < 4; e++) s[i][e] = 0.f;

        #pragma unroll
        for (int ks = 0; ks < 3; ks++) {
            #pragma unroll
            for (int np = 0; np < 8; np++) {
                const int krow = np * 16 + (lane & 7) + ((lane & 16) ? 8 : 0);
                const int kcol = ks * 16 + ((lane & 8) ? 8 : 0);
                const uint32_t off = (uint32_t)(krow * 56 + kcol) * 2;
                uint32_t kh4[4], kl4[4];
                ldmx4(kh4, sb + AT_KHI + off);
                ldmx4(kl4, sb + AT_KLO + off);
                mma16816(s[2*np],   qh[ks], kh4[0], kh4[1]);
                mma16816(s[2*np],   qh[ks], kl4[0], kl4[1]);
                mma16816(s[2*np],   ql[ks], kh4[0], kh4[1]);
                mma16816(s[2*np+1], qh[ks], kh4[2], kh4[3]);
                mma16816(s[2*np+1], qh[ks], kl4[2], kl4[3]);
                mma16816(s[2*np+1], ql[ks], kh4[2], kh4[3]);
            }
        }

        // scale + rel-pos bias + online softmax
        float mx0 = -1e30f, mx1 = -1e30f;
        #pragma unroll
        for (int nf = 0; nf < 16; nf++) {
            const int j0 = nf * 8 + (lane & 3) * 2;
            const int hm = kb * 4 + (j0 >> 5);
            const int wm = j0 & 31;
            const float* br0 = bias_s + (hn0 + 31 - hm) * 64 + (wn0 - wm + 31);
            const float* br1 = bias_s + (hn1 + 31 - hm) * 64 + (wn1 - wm + 31);
            s[nf][0] = s[nf][0] * ATT_SCALE + br0[0];
            s[nf][1] = s[nf][1] * ATT_SCALE + br0[-1];
            s[nf][2] = s[nf][2] * ATT_SCALE + br1[0];
            s[nf][3] = s[nf][3] * ATT_SCALE + br1[-1];
            mx0 = fmaxf(mx0, fmaxf(s[nf][0], s[nf][1]));
            mx1 = fmaxf(mx1, fmaxf(s[nf][2], s[nf][3]));
        }
        mx0 = fmaxf(mx0, __shfl_xor_sync(0xffffffffu, mx0, 1));
        mx0 = fmaxf(mx0, __shfl_xor_sync(0xffffffffu, mx0, 2));
        mx1 = fmaxf(mx1, __shfl_xor_sync(0xffffffffu, mx1, 1));
        mx1 = fmaxf(mx1, __shfl_xor_sync(0xffffffffu, mx1, 2));
        const float mn0 = fmaxf(mrow0, mx0), mn1 = fmaxf(mrow1, mx1);
        const float c0 = __expf(mrow0 - mn0), c1 = __expf(mrow1 - mn1);
        mrow0 = mn0; mrow1 = mn1;
        #pragma unroll
        for (int nf = 0; nf < 6; nf++) {
            of[nf][0] *= c0; of[nf][1] *= c0;
            of[nf][2] *= c1; of[nf][3] *= c1;
        }
        float sum0 = 0.f, sum1 = 0.f;
        #pragma unroll
        for (int nf = 0; nf < 16; nf++) {
            s[nf][0] = __expf(s[nf][0] - mn0); sum0 += s[nf][0];
            s[nf][1] = __expf(s[nf][1] - mn0); sum0 += s[nf][1];
            s[nf][2] = __expf(s[nf][2] - mn1); sum1 += s[nf][2];
            s[nf][3] = __expf(s[nf][3] - mn1); sum1 += s[nf][3];
        }
        sum0 += __shfl_xor_sync(0xffffffffu, sum0, 1);
        sum0 += __shfl_xor_sync(0xffffffffu, sum0, 2);
        sum1 += __shfl_xor_sync(0xffffffffu, sum1, 1);
        sum1 += __shfl_xor_sync(0xffffffffu, sum1, 2);
        lrow0 = lrow0 * c0 + sum0;
        lrow1 = lrow1 * c1 + sum1;

        // O += P V  (P c-frags -> a-frags, split hi/lo)
        #pragma unroll
        for (int ks = 0; ks < 8; ks++) {
            uint32_t ah[4], al[4];
            {
                const float f[8] = {s[2*ks][0],   s[2*ks][1],   s[2*ks][2],   s[2*ks][3],
                                    s[2*ks+1][0], s[2*ks+1][1], s[2*ks+1][2], s[2*ks+1][3]};
                #pragma unroll
                for (int i = 0; i < 4; i++) {
                    __nv_bfloat16 h0 = __float2bfloat16(f[2*i]);
                    __nv_bfloat16 h1 = __float2bfloat16(f[2*i+1]);
                    __nv_bfloat16 l0 = __float2bfloat16(f[2*i]   - __bfloat162float(h0));
                    __nv_bfloat16 l1 = __float2bfloat16(f[2*i+1] - __bfloat162float(h1));
                    __nv_bfloat162 hh(h0, h1), ll(l0, l1);
                    ah[i] = *(uint32_t*)&hh;
                    al[i] = *(uint32_t*)&ll;
                }
            }
            #pragma unroll
            for (int np = 0; np < 3; np++) {
                const int drow = np * 16 + (lane & 7) + ((lane & 16) ? 8 : 0);
                const int kc = ks * 16 + ((lane & 8) ? 8 : 0);
                const uint32_t off = (uint32_t)(drow * 136 + kc) * 2;
                uint32_t vh4[4], vl4[4];
                ldmx4(vh4, sb + AT_VHI + off);
                ldmx4(vl4, sb + AT_VLO + off);
                mma16816(of[2*np],   ah, vh4[0], vh4[1]);
                mma16816(of[2*np],   ah, vl4[0], vl4[1]);
                mma16816(of[2*np],   al, vh4[0], vh4[1]);
                mma16816(of[2*np+1], ah, vh4[2], vh4[3]);
                mma16816(of[2*np+1], ah, vl4[2], vl4[3]);
                mma16816(of[2*np+1], al, vh4[2], vh4[3]);
            }
        }
    }

    // normalize + transpose via smem + coalesced packed store
    const float inv0 = 1.f / lrow0, inv1 = 1.f / lrow1;
    __syncthreads();
    float* Os = (float*)smem;   // [48 d][132]
    #pragma unroll
    for (int nf = 0; nf < 6; nf++) {
        const int d0 = nf * 8 + (lane & 3) * 2;
        const int t0 = w * 16 + (lane >> 2);
        Os[ d0      * 132 + t0    ] = of[nf][0] * inv0;
        Os[(d0 + 1) * 132 + t0    ] = of[nf][1] * inv0;
        Os[ d0      * 132 + t0 + 8] = of[nf][2] * inv1;
        Os[(d0 + 1) * 132 + t0 + 8] = of[nf][3] * inv1;
    }
    __syncthreads();
    uint32_t* op = o + ((size_t)(b * MIDD + h * HDD)) * NN + qb * 128;
    #pragma unroll
    for (int i = 0; i < 24; i++) {
        const int u = tid + 256 * i;
        const int d = u >> 7, t = u & 127;
        op[(size_t)d * NN + t] = packsplit(Os[d * 132 + t]);
    }
}

// ---------------------------------------------------------------------------
// Launch sequence (kernel launches only: graph-capturable)
// ---------------------------------------------------------------------------
extern "C" void kernel_launch(void* const* d_in, const int* in_sizes, int n_in,
                              void* d_out, int out_size)
{
    const float* x     = (const float*)d_in[0];
    const float* rpb   = (const float*)d_in[1];
    const float* ln1_g = (const float*)d_in[3];
    const float* ln1_b = (const float*)d_in[4];
    const float* ln2_g = (const float*)d_in[5];
    const float* ln2_b = (const float*)d_in[6];
    const float* wq    = (const float*)d_in[7];
    const float* bq    = (const float*)d_in[8];
    const float* wkv   = (const float*)d_in[9];
    const float* bkv   = (const float*)d_in[10];
    const float* wproj = (const float*)d_in[11];
    const float* bproj = (const float*)d_in[12];
    const float* w1    = (const float*)d_in[13];
    const float* b1    = (const float*)d_in[14];
    const float* w2    = (const float*)d_in[15];
    const float* b2    = (const float*)d_in[16];
    float* out = (float*)d_out;

    uint32_t *p_lnp, *p_q, *p_kv, *p_ao, *p_mid;
    float *p_y1;
    __nv_bfloat16 *p_wh, *p_wl;
    cudaGetSymbolAddress((void**)&p_lnp, g_lnp);
    cudaGetSymbolAddress((void**)&p_q,   g_q);
    cudaGetSymbolAddress((void**)&p_kv,  g_kv);
    cudaGetSymbolAddress((void**)&p_ao,  g_ao);
    cudaGetSymbolAddress((void**)&p_y1,  g_y1);
    cudaGetSymbolAddress((void**)&p_mid, g_mid);
    cudaGetSymbolAddress((void**)&p_wh,  g_wh);
    cudaGetSymbolAddress((void**)&p_wl,  g_wl);

    cudaFuncSetAttribute(mma_gemm<1>, cudaFuncAttributeMaxDynamicSharedMemorySize, SM_GEMM_TOTAL);
    cudaFuncSetAttribute(mma_gemm<3>, cudaFuncAttributeMaxDynamicSharedMemorySize, SM_GEMM_TOTAL);
    cudaFuncSetAttribute(mma_gemm<4>, cudaFuncAttributeMaxDynamicSharedMemorySize, SM_GEMM_TOTAL);
    cudaFuncSetAttribute(attn_kernel, cudaFuncAttributeMaxDynamicSharedMemorySize, AT_TOTAL);

    // Weight splits (cheap; graph-capturable)
    wconv_kernel<<<(147456 + 255) / 256, 256>>>(wq,    p_wh + WOFF_Q,    p_wl + WOFF_Q,    147456);
    wconv_kernel<<<(294912 + 255) / 256, 256>>>(wkv,   p_wh + WOFF_KV,   p_wl + WOFF_KV,   294912);
    wconv_kernel<<<(147456 + 255) / 256, 256>>>(wproj, p_wh + WOFF_PROJ, p_wl + WOFF_PROJ, 147456);
    wconv_kernel<<<(589824 + 255) / 256, 256>>>(w1,    p_wh + WOFF_W1,   p_wl + WOFF_W1,   589824);
    wconv_kernel<<<(589824 + 255) / 256, 256>>>(w2,    p_wh + WOFF_W2,   p_wl + WOFF_W2,   589824);

    const dim3 lnGrid(NN / 256, BB);

    // LN1 -> packed
    ln_kernel<<<lnGrid, 256>>>(x, ln1_g, ln1_b, p_lnp);
    // Q = wq @ ln1 + bq -> packed
    mma_gemm<3><<<dim3(NN/128, MIDD/128,   BB), 256, SM_GEMM_TOTAL>>>(
        p_wh + WOFF_Q,  p_wl + WOFF_Q,  p_lnp, bq,  nullptr, p_q,  MIDD,   CC);
    // KV -> packed
    mma_gemm<3><<<dim3(NN/128, 2*MIDD/128, BB), 256, SM_GEMM_TOTAL>>>(
        p_wh + WOFF_KV, p_wl + WOFF_KV, p_lnp, bkv, nullptr, p_kv, 2*MIDD, CC);
    // Attention -> packed
    attn_kernel<<<dim3(NN/128, NHH, BB), 256, AT_TOTAL>>>(p_q, p_kv, rpb, p_ao);
    // y1 = x + wproj @ ao + bproj  (fp32)
    mma_gemm<1><<<dim3(NN/128, CC/128, BB), 256, SM_GEMM_TOTAL>>>(
        p_wh + WOFF_PROJ, p_wl + WOFF_PROJ, p_ao, bproj, x, p_y1, CC, MIDD);
    // LN2 -> packed
    ln_kernel<<<lnGrid, 256>>>(p_y1, ln2_g, ln2_b, p_lnp);
    // hidden = gelu(w1 @ ln2 + b1) -> packed
    mma_gemm<4><<<dim3(NN/128, HIDD/128, BB), 256, SM_GEMM_TOTAL>>>(
        p_wh + WOFF_W1, p_wl + WOFF_W1, p_lnp, b1, nullptr, p_mid, HIDD, CC);
    // out = y1 + w2 @ hidden + b2  (fp32)
    mma_gemm<1><<<dim3(NN/128, CC/128, BB), 256, SM_GEMM_TOTAL>>>(
        p_wh + WOFF_W2, p_wl + WOFF_W2, p_mid, b2, p_y1, out, CC, HIDD);
}